// round 1
// baseline (speedup 1.0000x reference)
#include <cuda_runtime.h>
#include <cuda_fp16.h>
#include <cstdint>

#define B_      1024
#define N_      4096
#define L_      8
#define K_      16
#define G_      8          // batch rows per block
#define THREADS_ 512
#define NBLOCKS_ (B_ / G_) // 128

// Packed uint16 indices (values in [0, 4096)): 8*4096*16*2 = 1 MB scratch.
__device__ __align__(16) uint16_t g_src16[L_ * N_ * K_];

__global__ void prep_src16(const int* __restrict__ src) {
    int i = blockIdx.x * blockDim.x + threadIdx.x;
    int base = i * 4;
    if (base < L_ * N_ * K_) {
        int4 v = *reinterpret_cast<const int4*>(src + base);
        ushort4 o = make_ushort4((uint16_t)v.x, (uint16_t)v.y,
                                 (uint16_t)v.z, (uint16_t)v.w);
        *reinterpret_cast<ushort4*>(g_src16 + base) = o;
    }
}

// One gather index serves all G=8 batch rows: one LDS.128 of [s][0..7] fp16,
// converted to fp32 and FMA'd into 8 accumulators.
__device__ __forceinline__ void gather_fma(const __half* __restrict__ cur,
                                           uint32_t s, float wk, float* acc) {
    uint4 v = *reinterpret_cast<const uint4*>(cur + s * G_);
    float2 f;
    f = __half22float2(*reinterpret_cast<__half2*>(&v.x));
    acc[0] = fmaf(f.x, wk, acc[0]); acc[1] = fmaf(f.y, wk, acc[1]);
    f = __half22float2(*reinterpret_cast<__half2*>(&v.y));
    acc[2] = fmaf(f.x, wk, acc[2]); acc[3] = fmaf(f.y, wk, acc[3]);
    f = __half22float2(*reinterpret_cast<__half2*>(&v.z));
    acc[4] = fmaf(f.x, wk, acc[4]); acc[5] = fmaf(f.y, wk, acc[5]);
    f = __half22float2(*reinterpret_cast<__half2*>(&v.w));
    acc[6] = fmaf(f.x, wk, acc[6]); acc[7] = fmaf(f.y, wk, acc[7]);
}

__global__ void __launch_bounds__(THREADS_, 1)
genome_kernel(const float* __restrict__ x, const float* __restrict__ w,
              float* __restrict__ out) {
    extern __shared__ __half sm[];
    __half* bufA = sm;               // [N_][G_]
    __half* bufB = sm + N_ * G_;     // double buffer
    const int b0 = blockIdx.x * G_;

    // Load this block's 8 batch rows of x into bufA (fp16, [n][g] layout).
    for (int n = threadIdx.x; n < N_; n += THREADS_) {
        __half tmp[G_];
        #pragma unroll
        for (int g = 0; g < G_; g++)
            tmp[g] = __float2half_rn(x[(size_t)(b0 + g) * N_ + n]);
        *reinterpret_cast<uint4*>(bufA + (size_t)n * G_) =
            *reinterpret_cast<uint4*>(tmp);
    }
    __syncthreads();

    #pragma unroll 1
    for (int l = 0; l < L_; l++) {
        const __half* cur = (l & 1) ? bufB : bufA;
        __half*       nxt = (l & 1) ? bufA : bufB;
        const uint4*  srcv = reinterpret_cast<const uint4*>(g_src16) + (size_t)l * N_ * 2;
        const float4* wv   = reinterpret_cast<const float4*>(w) + (size_t)l * N_ * 4;
        const bool last = (l == L_ - 1);

        for (int n = threadIdx.x; n < N_; n += THREADS_) {
            // 16 indices (32 B) + 16 weights (64 B), fully coalesced
            uint4  s01 = srcv[n * 2 + 0];
            uint4  s23 = srcv[n * 2 + 1];
            float4 w0 = wv[n * 4 + 0];
            float4 w1 = wv[n * 4 + 1];
            float4 w2 = wv[n * 4 + 2];
            float4 w3 = wv[n * 4 + 3];

            float acc[G_];
            #pragma unroll
            for (int g = 0; g < G_; g++) acc[g] = 0.0f;

            gather_fma(cur, s01.x & 0xFFFFu, w0.x, acc);
            gather_fma(cur, s01.x >> 16,     w0.y, acc);
            gather_fma(cur, s01.y & 0xFFFFu, w0.z, acc);
            gather_fma(cur, s01.y >> 16,     w0.w, acc);
            gather_fma(cur, s01.z & 0xFFFFu, w1.x, acc);
            gather_fma(cur, s01.z >> 16,     w1.y, acc);
            gather_fma(cur, s01.w & 0xFFFFu, w1.z, acc);
            gather_fma(cur, s01.w >> 16,     w1.w, acc);
            gather_fma(cur, s23.x & 0xFFFFu, w2.x, acc);
            gather_fma(cur, s23.x >> 16,     w2.y, acc);
            gather_fma(cur, s23.y & 0xFFFFu, w2.z, acc);
            gather_fma(cur, s23.y >> 16,     w2.w, acc);
            gather_fma(cur, s23.z & 0xFFFFu, w3.x, acc);
            gather_fma(cur, s23.z >> 16,     w3.y, acc);
            gather_fma(cur, s23.w & 0xFFFFu, w3.z, acc);
            gather_fma(cur, s23.w >> 16,     w3.w, acc);

            float r[G_];
            #pragma unroll
            for (int g = 0; g < G_; g++)
                asm("tanh.approx.f32 %0, %1;" : "=f"(r[g]) : "f"(acc[g]));

            if (!last) {
                __half2 p[G_ / 2];
                #pragma unroll
                for (int g = 0; g < G_ / 2; g++)
                    p[g] = __floats2half2_rn(r[2 * g], r[2 * g + 1]);
                *reinterpret_cast<uint4*>(nxt + (size_t)n * G_) =
                    *reinterpret_cast<const uint4*>(p);
            } else {
                // Final layer: write fp32 result straight to global (skips one
                // fp16 quantization and the extra copy-out pass).
                #pragma unroll
                for (int g = 0; g < G_; g++)
                    out[(size_t)(b0 + g) * N_ + n] = r[g];
            }
        }
        __syncthreads();
    }
}

extern "C" void kernel_launch(void* const* d_in, const int* in_sizes, int n_in,
                              void* d_out, int out_size) {
    const float* x   = (const float*)d_in[0];
    const int*   src = (const int*)d_in[1];
    const float* w   = (const float*)d_in[2];
    float*       out = (float*)d_out;

    // Pack indices to uint16 (deterministic, graph-capturable, no allocs).
    int total4 = (L_ * N_ * K_) / 4;
    prep_src16<<<(total4 + 255) / 256, 256>>>(src);

    size_t smem = (size_t)2 * N_ * G_ * sizeof(__half);  // 128 KB
    cudaFuncSetAttribute(genome_kernel,
                         cudaFuncAttributeMaxDynamicSharedMemorySize, (int)smem);
    genome_kernel<<<NBLOCKS_, THREADS_, smem>>>(x, w, out);
}